// round 15
// baseline (speedup 1.0000x reference)
#include <cuda_runtime.h>
#include <math.h>

// HawkesPointProcess: B=8, N=4096. One CTA per batch row, 1024 threads (32
// warps), 4 elements/thread. R12 structure (tid-0 param hoist + smem
// broadcast, comp chain from decay factors, warp0-only mid scan, fused
// single-scalar reduction) with a polynomial softplus shortening the tid-0
// preamble that gates BAR0.
//
//   A_i = e_i*(A_{i-1}+1), e_i = exp(-beta*(t_i - t_{i-1})), e_0 := 0
//   lamb_i = A_i*alpha*beta + mu
//   out[b] = sum_i log(lamb_i+1e-8)*m_i + alpha*(sum_i m_i*exp(-beta*(t1-t_i)) - sum_i m_i)
//            - (t1-t0)*mu      (identical algebra to the reference for binary mask)

#define NT 1024
#define NW 32
#define CHUNK 4      // NT*CHUNK == N == 4096

__device__ __forceinline__ float softplus_poly(float x) {
    // Taylor of log(1+e^x) about 0; |x|<0.5 -> abs err < 4e-6.
    // Uniform fallback (no divergence risk; executed by one thread anyway).
    if (fabsf(x) < 0.5f) {
        const float x2 = x * x;
        return fmaf(0.5f, x,
               fmaf(x2, fmaf(x2, fmaf(x2, 3.4722222e-4f, -5.2083333e-3f), 0.125f),
                    0.69314718f));
    }
    return __logf(1.0f + __expf(x));
}

__global__ __launch_bounds__(NT, 1)
void hawkes_kernel(const float* __restrict__ et,
                   const float* __restrict__ mask,
                   const float* __restrict__ t0v,
                   const float* __restrict__ t1v,
                   const float* __restrict__ mu_raw,
                   const float* __restrict__ alpha_raw,
                   const float* __restrict__ beta_raw,
                   float* __restrict__ out,
                   int N) {
    const int b    = blockIdx.x;
    const int tid  = threadIdx.x;
    const int lane = tid & 31;
    const int warp = tid >> 5;

    const float* t = et   + (size_t)b * N;
    const float* m = mask + (size_t)b * N;

    __shared__ float sp[6];       // 0:mu 1:mu+1e-8 2:alpha 3:-beta 4:alpha*beta 5:T1
    __shared__ float sG[NW], sH[NW];
    __shared__ float rv[NW];

    const int base = tid * CHUNK;

    // Issue the bulk loads FIRST so they fly during the param preamble.
    const float4 t4 = *reinterpret_cast<const float4*>(t + base);
    const float4 m4 = *reinterpret_cast<const float4*>(m + base);
    const float tprev = (tid == 0) ? t4.x : t[base - 1];

    // One thread computes the params (3 parallel LDGs + short FMA trees —
    // no MUFU on the barrier-gating path) and broadcasts via smem.
    if (tid == 0) {
        const float xr = mu_raw[0];
        const float ar = alpha_raw[0];
        const float br = beta_raw[0];
        const float T1 = t1v[b];
        const float mu    = softplus_poly(xr);
        const float alpha = softplus_poly(ar);
        const float beta  = softplus_poly(br);
        sp[0] = mu;
        sp[1] = mu + 1e-8f;
        sp[2] = alpha;
        sp[3] = -beta;
        sp[4] = alpha * beta;
        sp[5] = T1;
    }
    __syncthreads();                                          // BAR 0
    const float mu8   = sp[1];
    const float alpha = sp[2];
    const float nb    = sp[3];
    const float ab    = sp[4];
    const float T1    = sp[5];

    // Per-element decay factors (4 MUFU exps). Keep raw e1..e3 for the
    // compensator chain; zero e0 only in the scan coefficients.
    float e0 = __expf(nb * (t4.x - tprev));
    const float e1 = __expf(nb * (t4.y - t4.x));
    const float e2 = __expf(nb * (t4.z - t4.y));
    const float e3 = __expf(nb * (t4.w - t4.z));
    if (tid == 0) e0 = 0.0f;   // global element 0: A_0 = 0

    // Per-element affine coefficients: A_k = P_k*A_in + H_k.
    const float P0 = e0,      H0 = e0;
    const float P1 = e1 * P0; const float H1 = fmaf(e1, H0, e1);
    const float P2 = e2 * P1; const float H2 = fmaf(e2, H1, e2);
    const float P3 = e3 * P2; const float H3 = fmaf(e3, H2, e3);

    float G = P3, H = H3;

    // Compensator terms from ONE exp + the decay factors:
    //   c_k = exp(-beta*(T1 - t_k)); c_k = c_{k+1} * e_{k+1}.
    // For binary mask the reference term is exactly m_k * c_k.
    const float c3 = __expf(nb * (T1 - t4.w));
    const float c2 = c3 * e3;
    const float c1 = c2 * e2;
    const float c0 = c1 * e1;
    const float comp = fmaf(m4.x, c0, fmaf(m4.y, c1, fmaf(m4.z, c2, m4.w * c3)));
    const float msum = (m4.x + m4.y) + (m4.z + m4.w);

    // Inclusive warp scan over (G,H): compose(cur, prev) = (Gc*Gp, Gc*Hp+Hc).
    #pragma unroll
    for (int off = 1; off < 32; off <<= 1) {
        const float Gp = __shfl_up_sync(0xffffffffu, G, off);
        const float Hp = __shfl_up_sync(0xffffffffu, H, off);
        if (lane >= off) { H = fmaf(G, Hp, H); G *= Gp; }
    }
    float Gex = __shfl_up_sync(0xffffffffu, G, 1);   // lane-exclusive
    float Hex = __shfl_up_sync(0xffffffffu, H, 1);
    if (lane == 0) { Gex = 1.0f; Hex = 0.0f; }

    if (lane == 31) { sG[warp] = G; sH[warp] = H; }
    __syncthreads();                                          // BAR 1
    if (warp == 0) {
        float g = sG[lane], h = sH[lane];
        #pragma unroll
        for (int off = 1; off < 32; off <<= 1) {
            const float gp = __shfl_up_sync(0xffffffffu, g, off);
            const float hp = __shfl_up_sync(0xffffffffu, h, off);
            if (lane >= off) { h = fmaf(g, hp, h); g *= gp; }
        }
        sH[lane] = h;   // inclusive warp-prefix values (applied to A=0)
    }
    __syncthreads();                                          // BAR 2

    // State entering this thread's chunk.
    const float Aw   = (warp == 0) ? 0.0f : sH[warp - 1];
    const float A_in = fmaf(Gex, Aw, Hex);

    // Replay: 4 independent FMAs, product tree, single log (1 MUFU).
    const float l0 = fmaf(fmaf(P0, A_in, H0), ab, mu8);
    const float l1 = fmaf(fmaf(P1, A_in, H1), ab, mu8);
    const float l2 = fmaf(fmaf(P2, A_in, H2), ab, mu8);
    const float l3 = fmaf(fmaf(P3, A_in, H3), ab, mu8);
    const float f0 = fmaf(m4.x, l0 - 1.0f, 1.0f);   // lamb^m, m in {0,1}
    const float f1 = fmaf(m4.y, l1 - 1.0f, 1.0f);
    const float f2 = fmaf(m4.z, l2 - 1.0f, 1.0f);
    const float f3 = fmaf(m4.w, l3 - 1.0f, 1.0f);
    const float P  = (f0 * f1) * (f2 * f3);

    // Fused per-thread scalar.
    float v = fmaf(alpha, comp - msum, __logf(P));

    // Single-scalar two-level reduction.
    #pragma unroll
    for (int off = 16; off > 0; off >>= 1)
        v += __shfl_xor_sync(0xffffffffu, v, off);
    if (lane == 0) rv[warp] = v;
    __syncthreads();                                          // BAR 3

    if (warp == 0) {
        float s = rv[lane];
        #pragma unroll
        for (int off = 16; off > 0; off >>= 1)
            s += __shfl_xor_sync(0xffffffffu, s, off);
        if (lane == 0) {
            const float T0 = t0v[b];
            out[b] = s - (T1 - T0) * sp[0];
        }
    }
}

extern "C" void kernel_launch(void* const* d_in, const int* in_sizes, int n_in,
                              void* d_out, int out_size) {
    const float* event_times = (const float*)d_in[0];
    const float* input_mask  = (const float*)d_in[1];
    const float* t0          = (const float*)d_in[2];
    const float* t1          = (const float*)d_in[3];
    const float* mu          = (const float*)d_in[4];
    const float* alpha       = (const float*)d_in[5];
    const float* beta        = (const float*)d_in[6];
    float* out = (float*)d_out;

    const int B = in_sizes[2];      // t0 has B elements
    const int N = in_sizes[0] / B;  // 4096

    hawkes_kernel<<<B, NT>>>(event_times, input_mask, t0, t1,
                             mu, alpha, beta, out, N);
}

// round 16
// speedup vs baseline: 1.1587x; 1.1587x over previous
#include <cuda_runtime.h>
#include <math.h>

// HawkesPointProcess: B=8, N=4096. One CTA per batch row, 1024 threads (32
// warps), 4 elements/thread. R12 body with: warp-local lane-parallel params
// (no BAR0, no tid-0 serialization), tprev via shfl (lane0-only scalar LDG).
//
//   A_i = e_i*(A_{i-1}+1), e_i = exp(-beta*(t_i - t_{i-1})), e_0 := 0
//   lamb_i = A_i*alpha*beta + mu
//   out[b] = sum_i log(lamb_i+1e-8)*m_i + alpha*(sum_i m_i*exp(-beta*(t1-t_i)) - sum_i m_i)
//            - (t1-t0)*mu      (identical algebra to the reference for binary mask)

#define NT 1024
#define NW 32
#define CHUNK 4      // NT*CHUNK == N == 4096

__global__ __launch_bounds__(NT, 1)
void hawkes_kernel(const float* __restrict__ et,
                   const float* __restrict__ mask,
                   const float* __restrict__ t0v,
                   const float* __restrict__ t1v,
                   const float* __restrict__ mu_raw,
                   const float* __restrict__ alpha_raw,
                   const float* __restrict__ beta_raw,
                   float* __restrict__ out,
                   int N) {
    const int b    = blockIdx.x;
    const int tid  = threadIdx.x;
    const int lane = tid & 31;
    const int warp = tid >> 5;

    const float* t = et   + (size_t)b * N;
    const float* m = mask + (size_t)b * N;

    __shared__ float sG[NW], sH[NW];
    __shared__ float rv[NW];

    const int base = tid * CHUNK;

    // Bulk loads first — they fly while the params resolve.
    const float4 t4 = *reinterpret_cast<const float4*>(t + base);
    const float4 m4 = *reinterpret_cast<const float4*>(m + base);

    // Warp-local params: lanes 0-2 load mu/alpha/beta (L1-broadcast across
    // warps), softplus as TWO MUFU warp-ops, then 3 shfl broadcasts.
    // No barrier, no single-thread serialization.
    const float* pp = (lane == 0) ? mu_raw : (lane == 1) ? alpha_raw : beta_raw;
    const float pv  = (lane < 3) ? pp[0] : 0.0f;
    const float sv  = __logf(1.0f + __expf(pv));
    const float mu    = __shfl_sync(0xffffffffu, sv, 0);
    const float alpha = __shfl_sync(0xffffffffu, sv, 1);
    const float beta  = __shfl_sync(0xffffffffu, sv, 2);
    const float nb  = -beta;
    const float ab  = alpha * beta;
    const float mu8 = mu + 1e-8f;
    const float T1  = t1v[b];            // uniform LDG, L1-broadcast

    // tprev: previous thread's t4.w via shuffle; only lane 0 loads from GMEM.
    const float twp = __shfl_up_sync(0xffffffffu, t4.w, 1);
    float tprev;
    if (lane == 0) {
        tprev = (tid == 0) ? t4.x : t[base - 1];
    } else {
        tprev = twp;
    }

    // Per-element decay factors (4 MUFU exps). Keep raw e1..e3 for the
    // compensator chain; zero e0 only in the scan coefficients.
    float e0 = __expf(nb * (t4.x - tprev));
    const float e1 = __expf(nb * (t4.y - t4.x));
    const float e2 = __expf(nb * (t4.z - t4.y));
    const float e3 = __expf(nb * (t4.w - t4.z));
    if (tid == 0) e0 = 0.0f;   // global element 0: A_0 = 0

    // Per-element affine coefficients: A_k = P_k*A_in + H_k.
    const float P0 = e0,      H0 = e0;
    const float P1 = e1 * P0; const float H1 = fmaf(e1, H0, e1);
    const float P2 = e2 * P1; const float H2 = fmaf(e2, H1, e2);
    const float P3 = e3 * P2; const float H3 = fmaf(e3, H2, e3);

    float G = P3, H = H3;

    // Compensator terms from ONE exp + the decay factors:
    //   c_k = exp(-beta*(T1 - t_k)); c_k = c_{k+1} * e_{k+1}.
    // For binary mask the reference term is exactly m_k * c_k.
    const float c3 = __expf(nb * (T1 - t4.w));
    const float c2 = c3 * e3;
    const float c1 = c2 * e2;
    const float c0 = c1 * e1;
    const float comp = fmaf(m4.x, c0, fmaf(m4.y, c1, fmaf(m4.z, c2, m4.w * c3)));
    const float msum = (m4.x + m4.y) + (m4.z + m4.w);

    // Inclusive warp scan over (G,H): compose(cur, prev) = (Gc*Gp, Gc*Hp+Hc).
    #pragma unroll
    for (int off = 1; off < 32; off <<= 1) {
        const float Gp = __shfl_up_sync(0xffffffffu, G, off);
        const float Hp = __shfl_up_sync(0xffffffffu, H, off);
        if (lane >= off) { H = fmaf(G, Hp, H); G *= Gp; }
    }
    float Gex = __shfl_up_sync(0xffffffffu, G, 1);   // lane-exclusive
    float Hex = __shfl_up_sync(0xffffffffu, H, 1);
    if (lane == 0) { Gex = 1.0f; Hex = 0.0f; }

    if (lane == 31) { sG[warp] = G; sH[warp] = H; }
    __syncthreads();                                          // BAR 1
    if (warp == 0) {
        float g = sG[lane], h = sH[lane];
        #pragma unroll
        for (int off = 1; off < 32; off <<= 1) {
            const float gp = __shfl_up_sync(0xffffffffu, g, off);
            const float hp = __shfl_up_sync(0xffffffffu, h, off);
            if (lane >= off) { h = fmaf(g, hp, h); g *= gp; }
        }
        sH[lane] = h;   // inclusive warp-prefix values (applied to A=0)
    }
    __syncthreads();                                          // BAR 2

    // State entering this thread's chunk.
    const float Aw   = (warp == 0) ? 0.0f : sH[warp - 1];
    const float A_in = fmaf(Gex, Aw, Hex);

    // Replay: 4 independent FMAs, product tree, single log (1 MUFU).
    const float l0 = fmaf(fmaf(P0, A_in, H0), ab, mu8);
    const float l1 = fmaf(fmaf(P1, A_in, H1), ab, mu8);
    const float l2 = fmaf(fmaf(P2, A_in, H2), ab, mu8);
    const float l3 = fmaf(fmaf(P3, A_in, H3), ab, mu8);
    const float f0 = fmaf(m4.x, l0 - 1.0f, 1.0f);   // lamb^m, m in {0,1}
    const float f1 = fmaf(m4.y, l1 - 1.0f, 1.0f);
    const float f2 = fmaf(m4.z, l2 - 1.0f, 1.0f);
    const float f3 = fmaf(m4.w, l3 - 1.0f, 1.0f);
    const float P  = (f0 * f1) * (f2 * f3);

    // Fused per-thread scalar.
    float v = fmaf(alpha, comp - msum, __logf(P));

    // Single-scalar two-level reduction.
    #pragma unroll
    for (int off = 16; off > 0; off >>= 1)
        v += __shfl_xor_sync(0xffffffffu, v, off);
    if (lane == 0) rv[warp] = v;
    __syncthreads();                                          // BAR 3

    if (warp == 0) {
        float s = rv[lane];
        #pragma unroll
        for (int off = 16; off > 0; off >>= 1)
            s += __shfl_xor_sync(0xffffffffu, s, off);
        if (lane == 0) {
            const float T0 = t0v[b];
            out[b] = s - (T1 - T0) * mu;
        }
    }
}

extern "C" void kernel_launch(void* const* d_in, const int* in_sizes, int n_in,
                              void* d_out, int out_size) {
    const float* event_times = (const float*)d_in[0];
    const float* input_mask  = (const float*)d_in[1];
    const float* t0          = (const float*)d_in[2];
    const float* t1          = (const float*)d_in[3];
    const float* mu          = (const float*)d_in[4];
    const float* alpha       = (const float*)d_in[5];
    const float* beta        = (const float*)d_in[6];
    float* out = (float*)d_out;

    const int B = in_sizes[2];      // t0 has B elements
    const int N = in_sizes[0] / B;  // 4096

    hawkes_kernel<<<B, NT>>>(event_times, input_mask, t0, t1,
                             mu, alpha, beta, out, N);
}